// round 2
// baseline (speedup 1.0000x reference)
#include <cuda_runtime.h>
#include <math.h>

// Problem constants
#define BB    8
#define LLEN  384
#define HIDN  512
#define NHEAD 8
#define DHEAD 64
#define PROWS 768   // 2*MAX_SEQ_LEN
#define NBH   (BB*NHEAD)

// ---------------------------------------------------------------------------
// Scratch (device globals — no allocation allowed)
// ---------------------------------------------------------------------------
__device__ float g_q[BB*LLEN*HIDN];
__device__ float g_k[BB*LLEN*HIDN];
__device__ float g_v[BB*LLEN*HIDN];
__device__ float g_ctx[BB*LLEN*HIDN];
__device__ float g_r[PROWS*HIDN];            // pe @ Wr^T + br
__device__ float g_att[NBH*LLEN*LLEN];       // raw A scores, then softmax probs
__device__ float g_S[NBH*LLEN*PROWS];        // (q+vb) @ rW_h^T  (pre-shift)

// ---------------------------------------------------------------------------
// GEMM: C[M,512] = X[M,512] @ W[512,512]^T + bias   (row-major, K contiguous)
// BM=128, BN=64, BK=16, 128 threads, 8x8 per thread.
// ---------------------------------------------------------------------------
__global__ __launch_bounds__(128) void gemm_proj(const float* __restrict__ X,
                                                 const float* __restrict__ W,
                                                 const float* __restrict__ bias,
                                                 float* __restrict__ C) {
    __shared__ float Xs[16][132];
    __shared__ float Ws[16][68];
    const int t  = threadIdx.x;
    const int n0 = blockIdx.x * 64;
    const int m0 = blockIdx.y * 128;
    const int tx = t & 7, ty = t >> 3;

    float acc[8][8];
#pragma unroll
    for (int r = 0; r < 8; r++)
#pragma unroll
        for (int c = 0; c < 8; c++) acc[r][c] = 0.f;

    for (int k0 = 0; k0 < 512; k0 += 16) {
#pragma unroll
        for (int i = 0; i < 4; i++) {
            int idx = t + i * 128;
            int row = idx >> 2, kc = (idx & 3) << 2;
            float4 v = *(const float4*)(X + (size_t)(m0 + row) * 512 + k0 + kc);
            Xs[kc][row] = v.x; Xs[kc + 1][row] = v.y;
            Xs[kc + 2][row] = v.z; Xs[kc + 3][row] = v.w;
        }
#pragma unroll
        for (int i = 0; i < 2; i++) {
            int idx = t + i * 128;
            int row = idx >> 2, kc = (idx & 3) << 2;
            float4 v = *(const float4*)(W + (size_t)(n0 + row) * 512 + k0 + kc);
            Ws[kc][row] = v.x; Ws[kc + 1][row] = v.y;
            Ws[kc + 2][row] = v.z; Ws[kc + 3][row] = v.w;
        }
        __syncthreads();
#pragma unroll
        for (int k = 0; k < 16; k++) {
            float4 a0 = *(const float4*)&Xs[k][ty * 8];
            float4 a1 = *(const float4*)&Xs[k][ty * 8 + 4];
            float4 b0 = *(const float4*)&Ws[k][tx * 8];
            float4 b1 = *(const float4*)&Ws[k][tx * 8 + 4];
            float a[8]  = {a0.x, a0.y, a0.z, a0.w, a1.x, a1.y, a1.z, a1.w};
            float bb[8] = {b0.x, b0.y, b0.z, b0.w, b1.x, b1.y, b1.z, b1.w};
#pragma unroll
            for (int r = 0; r < 8; r++)
#pragma unroll
                for (int c = 0; c < 8; c++) acc[r][c] += a[r] * bb[c];
        }
        __syncthreads();
    }

    float4 bi0 = *(const float4*)(bias + n0 + tx * 8);
    float4 bi1 = *(const float4*)(bias + n0 + tx * 8 + 4);
    float bb[8] = {bi0.x, bi0.y, bi0.z, bi0.w, bi1.x, bi1.y, bi1.z, bi1.w};
#pragma unroll
    for (int r = 0; r < 8; r++) {
        size_t off = (size_t)(m0 + ty * 8 + r) * 512 + n0 + tx * 8;
        float4 o0, o1;
        o0.x = acc[r][0] + bb[0]; o0.y = acc[r][1] + bb[1];
        o0.z = acc[r][2] + bb[2]; o0.w = acc[r][3] + bb[3];
        o1.x = acc[r][4] + bb[4]; o1.y = acc[r][5] + bb[5];
        o1.z = acc[r][6] + bb[6]; o1.w = acc[r][7] + bb[7];
        *(float4*)(C + off)     = o0;
        *(float4*)(C + off + 4) = o1;
    }
}

// ---------------------------------------------------------------------------
// Batched attention GEMM (K = DHEAD = 64):
//   use_k=1: C[bh][i][j] = sum_d (q[b,h,i,d]+rowbias[h,d]) * k[b,h,j,d]   N=384
//   use_k=0: C[bh][i][p] = sum_d (q[b,h,i,d]+rowbias[h,d]) * rW[p,h,d]    N=768
// BM=128, BN=64, BK=16, 128 threads, 8x8 per thread.
// ---------------------------------------------------------------------------
__global__ __launch_bounds__(128) void attn_gemm(const float* __restrict__ rowbias,
                                                 int use_k,
                                                 float* __restrict__ Cout,
                                                 int Ncols) {
    __shared__ float Xs[16][132];
    __shared__ float Ws[16][68];
    const int t  = threadIdx.x;
    const int bh = blockIdx.z;
    const int b  = bh >> 3, h = bh & 7;
    const int n0 = blockIdx.x * 64;
    const int m0 = blockIdx.y * 128;
    const int tx = t & 7, ty = t >> 3;

    const float* Xb = g_q + (size_t)b * LLEN * HIDN + h * DHEAD;
    const float* Wb = use_k ? (g_k + (size_t)b * LLEN * HIDN + h * DHEAD)
                            : (g_r + h * DHEAD);
    float* C = Cout + (size_t)bh * LLEN * Ncols;

    float acc[8][8];
#pragma unroll
    for (int r = 0; r < 8; r++)
#pragma unroll
        for (int c = 0; c < 8; c++) acc[r][c] = 0.f;

    for (int k0 = 0; k0 < DHEAD; k0 += 16) {
#pragma unroll
        for (int i = 0; i < 4; i++) {
            int idx = t + i * 128;
            int row = idx >> 2, kc = (idx & 3) << 2;
            float4 v  = *(const float4*)(Xb + (size_t)(m0 + row) * HIDN + k0 + kc);
            float4 rb = *(const float4*)(rowbias + h * DHEAD + k0 + kc);
            Xs[kc][row]     = v.x + rb.x; Xs[kc + 1][row] = v.y + rb.y;
            Xs[kc + 2][row] = v.z + rb.z; Xs[kc + 3][row] = v.w + rb.w;
        }
#pragma unroll
        for (int i = 0; i < 2; i++) {
            int idx = t + i * 128;
            int row = idx >> 2, kc = (idx & 3) << 2;
            float4 v = *(const float4*)(Wb + (size_t)(n0 + row) * HIDN + k0 + kc);
            Ws[kc][row] = v.x; Ws[kc + 1][row] = v.y;
            Ws[kc + 2][row] = v.z; Ws[kc + 3][row] = v.w;
        }
        __syncthreads();
#pragma unroll
        for (int k = 0; k < 16; k++) {
            float4 a0 = *(const float4*)&Xs[k][ty * 8];
            float4 a1 = *(const float4*)&Xs[k][ty * 8 + 4];
            float4 b0 = *(const float4*)&Ws[k][tx * 8];
            float4 b1 = *(const float4*)&Ws[k][tx * 8 + 4];
            float a[8]  = {a0.x, a0.y, a0.z, a0.w, a1.x, a1.y, a1.z, a1.w};
            float bb[8] = {b0.x, b0.y, b0.z, b0.w, b1.x, b1.y, b1.z, b1.w};
#pragma unroll
            for (int r = 0; r < 8; r++)
#pragma unroll
                for (int c = 0; c < 8; c++) acc[r][c] += a[r] * bb[c];
        }
        __syncthreads();
    }

#pragma unroll
    for (int r = 0; r < 8; r++) {
        size_t off = (size_t)(m0 + ty * 8 + r) * Ncols + n0 + tx * 8;
        float4 o0 = {acc[r][0], acc[r][1], acc[r][2], acc[r][3]};
        float4 o1 = {acc[r][4], acc[r][5], acc[r][6], acc[r][7]};
        *(float4*)(C + off)     = o0;
        *(float4*)(C + off + 4) = o1;
    }
}

// ---------------------------------------------------------------------------
// Fused combine + rel-shift gather + mask + softmax.
// One block per (bh, i) row.  x_j = 0.125*(A[i,j] + S[i, j-i+384]) for j<sl.
// Writes probabilities back into g_att (zeros for masked j).
// ---------------------------------------------------------------------------
__global__ __launch_bounds__(128) void softmax_kernel(const int* __restrict__ seq_len) {
    __shared__ float red[128];
    const int i  = blockIdx.x;
    const int bh = blockIdx.y;
    const int b  = bh >> 3;
    const int sl = seq_len[b];
    const int t  = threadIdx.x;

    float* Arow       = g_att + ((size_t)bh * LLEN + i) * LLEN;
    const float* Srow = g_S + ((size_t)bh * LLEN + i) * PROWS + (LLEN - i);

    float x[3];
    float mx = -3.0e38f;
#pragma unroll
    for (int c = 0; c < 3; c++) {
        int j = t + c * 128;
        float v = (j < sl) ? 0.125f * (Arow[j] + Srow[j]) : -3.0e38f;
        x[c] = v;
        mx = fmaxf(mx, v);
    }
    red[t] = mx; __syncthreads();
    for (int s = 64; s > 0; s >>= 1) {
        if (t < s) red[t] = fmaxf(red[t], red[t + s]);
        __syncthreads();
    }
    mx = red[0]; __syncthreads();

    float p[3];
    float sum = 0.f;
#pragma unroll
    for (int c = 0; c < 3; c++) {
        int j = t + c * 128;
        p[c] = (j < sl) ? __expf(x[c] - mx) : 0.f;
        sum += p[c];
    }
    red[t] = sum; __syncthreads();
    for (int s = 64; s > 0; s >>= 1) {
        if (t < s) red[t] += red[t + s];
        __syncthreads();
    }
    float inv = 1.f / red[0];
#pragma unroll
    for (int c = 0; c < 3; c++) {
        int j = t + c * 128;
        Arow[j] = p[c] * inv;
    }
}

// ---------------------------------------------------------------------------
// PV GEMM (NN): ctx[b,i,h*64+d] = sum_j P[bh,i,j] * v[b,j,h*64+d]
// M=384, N=64, K=384.  BM=128, BN=64, BK=16, 128 threads, 8x8 per thread.
// ---------------------------------------------------------------------------
__global__ __launch_bounds__(128) void pv_gemm() {
    __shared__ float As[16][132];
    __shared__ float Bs[16][68];
    const int t  = threadIdx.x;
    const int bh = blockIdx.z;
    const int b  = bh >> 3, h = bh & 7;
    const int m0 = blockIdx.y * 128;
    const int tx = t & 7, ty = t >> 3;

    const float* Aatt = g_att + (size_t)bh * LLEN * LLEN;
    const float* Vb   = g_v + (size_t)b * LLEN * HIDN + h * DHEAD;
    float* Cb         = g_ctx + (size_t)b * LLEN * HIDN + h * DHEAD;

    float acc[8][8];
#pragma unroll
    for (int r = 0; r < 8; r++)
#pragma unroll
        for (int c = 0; c < 8; c++) acc[r][c] = 0.f;

    for (int k0 = 0; k0 < LLEN; k0 += 16) {
#pragma unroll
        for (int i = 0; i < 4; i++) {
            int idx = t + i * 128;
            int row = idx >> 2, kc = (idx & 3) << 2;
            float4 v = *(const float4*)(Aatt + (size_t)(m0 + row) * LLEN + k0 + kc);
            As[kc][row]     = v.x; As[kc + 1][row] = v.y;
            As[kc + 2][row] = v.z; As[kc + 3][row] = v.w;
        }
#pragma unroll
        for (int i = 0; i < 2; i++) {
            int idx = t + i * 128;
            int krow = idx >> 4, nc = (idx & 15) << 2;
            float4 v = *(const float4*)(Vb + (size_t)(k0 + krow) * HIDN + nc);
            *(float4*)&Bs[krow][nc] = v;
        }
        __syncthreads();
#pragma unroll
        for (int k = 0; k < 16; k++) {
            float4 a0 = *(const float4*)&As[k][ty * 8];
            float4 a1 = *(const float4*)&As[k][ty * 8 + 4];
            float4 b0 = *(const float4*)&Bs[k][tx * 8];
            float4 b1 = *(const float4*)&Bs[k][tx * 8 + 4];
            float a[8]  = {a0.x, a0.y, a0.z, a0.w, a1.x, a1.y, a1.z, a1.w};
            float bb[8] = {b0.x, b0.y, b0.z, b0.w, b1.x, b1.y, b1.z, b1.w};
#pragma unroll
            for (int r = 0; r < 8; r++)
#pragma unroll
                for (int c = 0; c < 8; c++) acc[r][c] += a[r] * bb[c];
        }
        __syncthreads();
    }

#pragma unroll
    for (int r = 0; r < 8; r++) {
        size_t off = (size_t)(m0 + ty * 8 + r) * HIDN + tx * 8;
        float4 o0 = {acc[r][0], acc[r][1], acc[r][2], acc[r][3]};
        float4 o1 = {acc[r][4], acc[r][5], acc[r][6], acc[r][7]};
        *(float4*)(Cb + off)     = o0;
        *(float4*)(Cb + off + 4) = o1;
    }
}

// ---------------------------------------------------------------------------
// Launcher
// ---------------------------------------------------------------------------
extern "C" void kernel_launch(void* const* d_in, const int* in_sizes, int n_in,
                              void* d_out, int out_size) {
    const float* key    = (const float*)d_in[0];
    const float* query  = (const float*)d_in[1];
    const float* value  = (const float*)d_in[2];
    const int*   seqlen = (const int*)  d_in[3];
    const float* pe     = (const float*)d_in[4];
    const float* Wk = (const float*)d_in[5],  *bk = (const float*)d_in[6];
    const float* Wq = (const float*)d_in[7],  *bq = (const float*)d_in[8];
    const float* Wv = (const float*)d_in[9],  *bv = (const float*)d_in[10];
    const float* Wr = (const float*)d_in[11], *br = (const float*)d_in[12];
    const float* u_bias = (const float*)d_in[13];
    const float* v_bias = (const float*)d_in[14];
    const float* Wf = (const float*)d_in[15], *bf = (const float*)d_in[16];
    float* out = (float*)d_out;

    float *dq, *dk, *dv, *dr, *dctx;
    cudaGetSymbolAddress((void**)&dq,   g_q);
    cudaGetSymbolAddress((void**)&dk,   g_k);
    cudaGetSymbolAddress((void**)&dv,   g_v);
    cudaGetSymbolAddress((void**)&dr,   g_r);
    cudaGetSymbolAddress((void**)&dctx, g_ctx);
    float *datt, *dS;
    cudaGetSymbolAddress((void**)&datt, g_att);
    cudaGetSymbolAddress((void**)&dS,   g_S);

    // Projections: [3072,512] @ [512,512]^T
    dim3 gProj(HIDN / 64, (BB * LLEN) / 128);
    gemm_proj<<<gProj, 128>>>(query, Wq, bq, dq);
    gemm_proj<<<gProj, 128>>>(key,   Wk, bk, dk);
    gemm_proj<<<gProj, 128>>>(value, Wv, bv, dv);
    // rW = pe @ Wr^T + br : [768,512]
    dim3 gR(HIDN / 64, PROWS / 128);
    gemm_proj<<<gR, 128>>>(pe, Wr, br, dr);

    // A-scores: (q+u) . k   -> g_att [bh,384,384]
    dim3 gA(LLEN / 64, LLEN / 128, NBH);
    attn_gemm<<<gA, 128>>>(u_bias, 1, datt, LLEN);
    // S: (q+vb) . rW_h      -> g_S [bh,384,768]
    dim3 gS(PROWS / 64, LLEN / 128, NBH);
    attn_gemm<<<gS, 128>>>(v_bias, 0, dS, PROWS);

    // combine + shift-gather + mask + softmax (probs overwrite g_att)
    dim3 gSm(LLEN, NBH);
    softmax_kernel<<<gSm, 128>>>(seqlen);

    // ctx = P @ V -> g_ctx in [b, i, hid] layout
    dim3 gPV(1, LLEN / 128, NBH);
    pv_gemm<<<gPV, 128>>>();

    // final projection: out = ctx @ Wf^T + bf
    gemm_proj<<<gProj, 128>>>(dctx, Wf, bf, out);
}

// round 3
// speedup vs baseline: 2.9329x; 2.9329x over previous
#include <cuda_runtime.h>
#include <cuda_fp16.h>
#include <math.h>

// Problem constants
#define BB    8
#define LLEN  384
#define HIDN  512
#define NHEAD 8
#define DHEAD 64
#define PROWS 768
#define NBH   (BB*NHEAD)

// GEMM tile config
#define BM 128
#define BN 64
#define BK 32
#define PAD 40   // smem row stride in halves (conflict-free for frag loads)

// ---------------------------------------------------------------------------
// Scratch (device globals)
// ---------------------------------------------------------------------------
__device__ __half g_xk[BB*LLEN*HIDN];
__device__ __half g_xq[BB*LLEN*HIDN];
__device__ __half g_xv[BB*LLEN*HIDN];
__device__ __half g_pe16[PROWS*HIDN];
__device__ __half g_wq16[HIDN*HIDN];
__device__ __half g_wk16[HIDN*HIDN];
__device__ __half g_wv16[HIDN*HIDN];
__device__ __half g_wr16[HIDN*HIDN];
__device__ __half g_wf16[HIDN*HIDN];

__device__ __half g_qu[BB*LLEN*HIDN];    // q + bq + u_bias
__device__ __half g_qv[BB*LLEN*HIDN];    // q + bq + v_bias
__device__ __half g_k16[BB*LLEN*HIDN];
__device__ __half g_v16[BB*LLEN*HIDN];
__device__ __half g_r16[PROWS*HIDN];     // pe @ Wr^T + br
__device__ __half g_vT[NBH*DHEAD*LLEN];  // v transposed per (b,h): [d][j]
__device__ __half g_ctx16[BB*LLEN*HIDN];
__device__ __half g_p16[NBH*LLEN*LLEN];  // softmax probs

__device__ float g_att[NBH*LLEN*LLEN];   // A scores fp32
__device__ float g_S[NBH*LLEN*PROWS];    // shifted-rel scores fp32

// ---------------------------------------------------------------------------
// fp32 -> fp16 convert (all tensors in one launch, blockIdx.y selects tensor)
// ---------------------------------------------------------------------------
struct CvtArgs {
    const float* src[9];
    __half*      dst[9];
    int          n[9];
};

__global__ __launch_bounds__(256) void cvt_kernel(CvtArgs a) {
    int ti = blockIdx.y;
    int n  = a.n[ti];
    int i  = (blockIdx.x * 256 + threadIdx.x) * 8;
    if (i >= n) return;
    const float4* s = (const float4*)(a.src[ti] + i);
    float4 x = s[0], y = s[1];
    __half2 h0 = __floats2half2_rn(x.x, x.y);
    __half2 h1 = __floats2half2_rn(x.z, x.w);
    __half2 h2 = __floats2half2_rn(y.x, y.y);
    __half2 h3 = __floats2half2_rn(y.z, y.w);
    uint4 o;
    o.x = *(unsigned*)&h0; o.y = *(unsigned*)&h1;
    o.z = *(unsigned*)&h2; o.w = *(unsigned*)&h3;
    *(uint4*)(a.dst[ti] + i) = o;
}

// ---------------------------------------------------------------------------
// mma helper: m16n8k16 fp16 -> fp32
// ---------------------------------------------------------------------------
__device__ __forceinline__ void mma16816(float* c, const unsigned* a, const unsigned* b) {
    asm volatile(
        "mma.sync.aligned.m16n8k16.row.col.f32.f16.f16.f32 "
        "{%0,%1,%2,%3}, {%4,%5,%6,%7}, {%8,%9}, {%0,%1,%2,%3};\n"
        : "+f"(c[0]), "+f"(c[1]), "+f"(c[2]), "+f"(c[3])
        : "r"(a[0]), "r"(a[1]), "r"(a[2]), "r"(a[3]), "r"(b[0]), "r"(b[1]));
}

// ---------------------------------------------------------------------------
// Tensor-core GEMM: C[M,N] = A[M,K] @ B[N,K]^T (+ epilogue)
// BM=128 BN=64 BK=32, 256 threads (8 warps: 4 x 2), double-buffered smem.
// EPI: 0 = fp32 + bias, 1 = fp16 + bias, 2 = dual fp16 (bias+ub / bias+vb),
//      3 = fp32 raw, 4 = fp16 raw
// Batch: z decomposed as (z>>3, z&7) with separate strides.
// ---------------------------------------------------------------------------
template<int EPI>
__global__ __launch_bounds__(256) void gemm16(
    const __half* __restrict__ A, int lda, size_t sA1, size_t sA2,
    const __half* __restrict__ B, int ldb, size_t sB1, size_t sB2,
    void* __restrict__ C0, void* __restrict__ C1, int ldc, size_t sC1, size_t sC2,
    const float* __restrict__ bias, const float* __restrict__ ub,
    const float* __restrict__ vb, int K)
{
    __shared__ __align__(16) __half As[2][BM * PAD];
    __shared__ __align__(16) __half Bs[2][BN * PAD];

    const int t    = threadIdx.x;
    const int warp = t >> 5, lane = t & 31;
    const int wm   = warp >> 1, wn = warp & 1;
    const int g    = lane >> 2, tg = lane & 3;
    const int z    = blockIdx.z;
    const int zb   = z >> 3, zh = z & 7;

    A += (size_t)zb * sA1 + (size_t)zh * sA2;
    B += (size_t)zb * sB1 + (size_t)zh * sB2;
    const size_t Coff = (size_t)zb * sC1 + (size_t)zh * sC2;

    const int m0 = blockIdx.y * BM;
    const int n0 = blockIdx.x * BN;

    const int arow = t >> 2, achk = t & 3;
    const __half* Ag  = A + (size_t)(m0 + arow)      * lda + achk * 8;
    const __half* Ag2 = A + (size_t)(m0 + arow + 64) * lda + achk * 8;
    const __half* Bg  = B + (size_t)(n0 + arow)      * ldb + achk * 8;

    float acc[2][4][4];
#pragma unroll
    for (int mi = 0; mi < 2; mi++)
#pragma unroll
        for (int ni = 0; ni < 4; ni++)
#pragma unroll
            for (int u = 0; u < 4; u++) acc[mi][ni][u] = 0.f;

    const int nk = K / BK;
    uint4 ra0 = *(const uint4*)Ag;
    uint4 ra1 = *(const uint4*)Ag2;
    uint4 rb  = *(const uint4*)Bg;
    *(uint4*)&As[0][arow * PAD + achk * 8]        = ra0;
    *(uint4*)&As[0][(arow + 64) * PAD + achk * 8] = ra1;
    *(uint4*)&Bs[0][arow * PAD + achk * 8]        = rb;
    __syncthreads();

    for (int kt = 0; kt < nk; kt++) {
        const int cur = kt & 1;
        if (kt + 1 < nk) {
            ra0 = *(const uint4*)(Ag  + (size_t)(kt + 1) * BK);
            ra1 = *(const uint4*)(Ag2 + (size_t)(kt + 1) * BK);
            rb  = *(const uint4*)(Bg  + (size_t)(kt + 1) * BK);
        }
#pragma unroll
        for (int ks = 0; ks < 2; ks++) {
            const int k0 = ks * 16;
            unsigned af[2][4], bf[4][2];
#pragma unroll
            for (int mi = 0; mi < 2; mi++) {
                const __half* base = &As[cur][(wm * 32 + mi * 16 + g) * PAD + k0 + tg * 2];
                af[mi][0] = *(const unsigned*)base;
                af[mi][1] = *(const unsigned*)(base + 8 * PAD);
                af[mi][2] = *(const unsigned*)(base + 8);
                af[mi][3] = *(const unsigned*)(base + 8 * PAD + 8);
            }
#pragma unroll
            for (int ni = 0; ni < 4; ni++) {
                const __half* base = &Bs[cur][(wn * 32 + ni * 8 + g) * PAD + k0 + tg * 2];
                bf[ni][0] = *(const unsigned*)base;
                bf[ni][1] = *(const unsigned*)(base + 8);
            }
#pragma unroll
            for (int mi = 0; mi < 2; mi++)
#pragma unroll
                for (int ni = 0; ni < 4; ni++)
                    mma16816(acc[mi][ni], af[mi], bf[ni]);
        }
        if (kt + 1 < nk) {
            const int nxt = cur ^ 1;
            *(uint4*)&As[nxt][arow * PAD + achk * 8]        = ra0;
            *(uint4*)&As[nxt][(arow + 64) * PAD + achk * 8] = ra1;
            *(uint4*)&Bs[nxt][arow * PAD + achk * 8]        = rb;
            __syncthreads();
        }
    }

    // Epilogue
#pragma unroll
    for (int mi = 0; mi < 2; mi++) {
        const int r0 = m0 + wm * 32 + mi * 16 + g;
#pragma unroll
        for (int ni = 0; ni < 4; ni++) {
            const int cb = n0 + wn * 32 + ni * 8 + tg * 2;
            float* ac = acc[mi][ni];
            const size_t o0 = Coff + (size_t)r0 * ldc + cb;
            const size_t o1 = Coff + (size_t)(r0 + 8) * ldc + cb;
            if (EPI == 3) {
                *(float2*)((float*)C0 + o0) = make_float2(ac[0], ac[1]);
                *(float2*)((float*)C0 + o1) = make_float2(ac[2], ac[3]);
            } else if (EPI == 0) {
                const float b0 = bias[cb], b1 = bias[cb + 1];
                *(float2*)((float*)C0 + o0) = make_float2(ac[0] + b0, ac[1] + b1);
                *(float2*)((float*)C0 + o1) = make_float2(ac[2] + b0, ac[3] + b1);
            } else if (EPI == 1) {
                const float b0 = bias[cb], b1 = bias[cb + 1];
                *(__half2*)((__half*)C0 + o0) = __floats2half2_rn(ac[0] + b0, ac[1] + b1);
                *(__half2*)((__half*)C0 + o1) = __floats2half2_rn(ac[2] + b0, ac[3] + b1);
            } else if (EPI == 4) {
                *(__half2*)((__half*)C0 + o0) = __floats2half2_rn(ac[0], ac[1]);
                *(__half2*)((__half*)C0 + o1) = __floats2half2_rn(ac[2], ac[3]);
            } else {  // dual
                const float bb0 = bias[cb], bb1 = bias[cb + 1];
                const float u0 = bb0 + ub[cb], u1 = bb1 + ub[cb + 1];
                const float v0 = bb0 + vb[cb], v1 = bb1 + vb[cb + 1];
                *(__half2*)((__half*)C0 + o0) = __floats2half2_rn(ac[0] + u0, ac[1] + u1);
                *(__half2*)((__half*)C0 + o1) = __floats2half2_rn(ac[2] + u0, ac[3] + u1);
                *(__half2*)((__half*)C1 + o0) = __floats2half2_rn(ac[0] + v0, ac[1] + v1);
                *(__half2*)((__half*)C1 + o1) = __floats2half2_rn(ac[2] + v0, ac[3] + v1);
            }
        }
    }
}

// ---------------------------------------------------------------------------
// Transpose V per (b,h): vT[bh][d][j] = v16[b*384+j][h*64+d]
// grid (6, 64), 256 threads, 64x64 tiles
// ---------------------------------------------------------------------------
__global__ __launch_bounds__(256) void transpose_v() {
    __shared__ __half tile[64][72];
    const int z = blockIdx.y, b = z >> 3, h = z & 7;
    const int j0 = blockIdx.x * 64;
    const int t = threadIdx.x;
#pragma unroll
    for (int it = 0; it < 2; it++) {
        int idx = t + it * 256;
        int j = idx >> 3, ch = idx & 7;
        uint4 val = *(const uint4*)(g_v16 + (size_t)(b * LLEN + j0 + j) * HIDN + h * 64 + ch * 8);
        *(uint4*)&tile[j][ch * 8] = val;
    }
    __syncthreads();
#pragma unroll
    for (int it = 0; it < 2; it++) {
        int idx = t + it * 256;
        int d = idx >> 3, ch = idx & 7;
        __half tmp[8];
#pragma unroll
        for (int u = 0; u < 8; u++) tmp[u] = tile[ch * 8 + u][d];
        *(uint4*)(g_vT + (size_t)(z * 64 + d) * LLEN + j0 + ch * 8) = *(uint4*)tmp;
    }
}

// ---------------------------------------------------------------------------
// Fused combine + rel-shift gather + mask + softmax -> fp16 probs
// ---------------------------------------------------------------------------
__global__ __launch_bounds__(128) void softmax_kernel(const int* __restrict__ seq_len) {
    __shared__ float red[128];
    const int i  = blockIdx.x;
    const int bh = blockIdx.y;
    const int b  = bh >> 3;
    const int sl = seq_len[b];
    const int t  = threadIdx.x;

    const float* Arow = g_att + ((size_t)bh * LLEN + i) * LLEN;
    const float* Srow = g_S + ((size_t)bh * LLEN + i) * PROWS + (LLEN - i);
    __half* Prow      = g_p16 + ((size_t)bh * LLEN + i) * LLEN;

    float x[3];
    float mx = -3.0e38f;
#pragma unroll
    for (int c = 0; c < 3; c++) {
        int j = t + c * 128;
        float v = (j < sl) ? 0.125f * (Arow[j] + Srow[j]) : -3.0e38f;
        x[c] = v;
        mx = fmaxf(mx, v);
    }
    red[t] = mx; __syncthreads();
    for (int s = 64; s > 0; s >>= 1) {
        if (t < s) red[t] = fmaxf(red[t], red[t + s]);
        __syncthreads();
    }
    mx = red[0]; __syncthreads();

    float p[3];
    float sum = 0.f;
#pragma unroll
    for (int c = 0; c < 3; c++) {
        int j = t + c * 128;
        p[c] = (j < sl) ? __expf(x[c] - mx) : 0.f;
        sum += p[c];
    }
    red[t] = sum; __syncthreads();
    for (int s = 64; s > 0; s >>= 1) {
        if (t < s) red[t] += red[t + s];
        __syncthreads();
    }
    const float inv = 1.f / red[0];
#pragma unroll
    for (int c = 0; c < 3; c++) {
        int j = t + c * 128;
        Prow[j] = __float2half(p[c] * inv);
    }
}

// ---------------------------------------------------------------------------
// Launcher
// ---------------------------------------------------------------------------
extern "C" void kernel_launch(void* const* d_in, const int* in_sizes, int n_in,
                              void* d_out, int out_size) {
    const float* key    = (const float*)d_in[0];
    const float* query  = (const float*)d_in[1];
    const float* value  = (const float*)d_in[2];
    const int*   seqlen = (const int*)  d_in[3];
    const float* pe     = (const float*)d_in[4];
    const float* Wk = (const float*)d_in[5],  *bk = (const float*)d_in[6];
    const float* Wq = (const float*)d_in[7],  *bq = (const float*)d_in[8];
    const float* Wv = (const float*)d_in[9],  *bv = (const float*)d_in[10];
    const float* Wr = (const float*)d_in[11], *br = (const float*)d_in[12];
    const float* u_bias = (const float*)d_in[13];
    const float* v_bias = (const float*)d_in[14];
    const float* Wf = (const float*)d_in[15], *bf = (const float*)d_in[16];
    float* out = (float*)d_out;

    __half *xk, *xq, *xv, *pe16, *wq16, *wk16, *wv16, *wr16, *wf16;
    __half *qu, *qv, *k16, *v16, *r16, *vT, *ctx16, *p16;
    float *att, *S;
    cudaGetSymbolAddress((void**)&xk,   g_xk);
    cudaGetSymbolAddress((void**)&xq,   g_xq);
    cudaGetSymbolAddress((void**)&xv,   g_xv);
    cudaGetSymbolAddress((void**)&pe16, g_pe16);
    cudaGetSymbolAddress((void**)&wq16, g_wq16);
    cudaGetSymbolAddress((void**)&wk16, g_wk16);
    cudaGetSymbolAddress((void**)&wv16, g_wv16);
    cudaGetSymbolAddress((void**)&wr16, g_wr16);
    cudaGetSymbolAddress((void**)&wf16, g_wf16);
    cudaGetSymbolAddress((void**)&qu,   g_qu);
    cudaGetSymbolAddress((void**)&qv,   g_qv);
    cudaGetSymbolAddress((void**)&k16,  g_k16);
    cudaGetSymbolAddress((void**)&v16,  g_v16);
    cudaGetSymbolAddress((void**)&r16,  g_r16);
    cudaGetSymbolAddress((void**)&vT,   g_vT);
    cudaGetSymbolAddress((void**)&ctx16,g_ctx16);
    cudaGetSymbolAddress((void**)&p16,  g_p16);
    cudaGetSymbolAddress((void**)&att,  g_att);
    cudaGetSymbolAddress((void**)&S,    g_S);

    // 1. convert everything to fp16
    CvtArgs ca;
    ca.src[0] = key;   ca.dst[0] = xk;   ca.n[0] = BB*LLEN*HIDN;
    ca.src[1] = query; ca.dst[1] = xq;   ca.n[1] = BB*LLEN*HIDN;
    ca.src[2] = value; ca.dst[2] = xv;   ca.n[2] = BB*LLEN*HIDN;
    ca.src[3] = pe;    ca.dst[3] = pe16; ca.n[3] = PROWS*HIDN;
    ca.src[4] = Wq;    ca.dst[4] = wq16; ca.n[4] = HIDN*HIDN;
    ca.src[5] = Wk;    ca.dst[5] = wk16; ca.n[5] = HIDN*HIDN;
    ca.src[6] = Wv;    ca.dst[6] = wv16; ca.n[6] = HIDN*HIDN;
    ca.src[7] = Wr;    ca.dst[7] = wr16; ca.n[7] = HIDN*HIDN;
    ca.src[8] = Wf;    ca.dst[8] = wf16; ca.n[8] = HIDN*HIDN;
    cvt_kernel<<<dim3(768, 9), 256>>>(ca);

    const size_t MB  = (size_t)LLEN * HIDN;          // 196608 (per-batch stride in q/k/v)
    const size_t ATT = (size_t)LLEN * LLEN;          // 147456
    const size_t SST = (size_t)LLEN * PROWS;         // 294912

    // 2. projections
    dim3 gP(HIDN / BN, (BB * LLEN) / BM);
    gemm16<2><<<gP, 256>>>(xq, HIDN, 0, 0, wq16, HIDN, 0, 0,
                           qu, qv, HIDN, 0, 0, bq, u_bias, v_bias, HIDN);
    gemm16<1><<<gP, 256>>>(xk, HIDN, 0, 0, wk16, HIDN, 0, 0,
                           k16, nullptr, HIDN, 0, 0, bk, nullptr, nullptr, HIDN);
    gemm16<1><<<gP, 256>>>(xv, HIDN, 0, 0, wv16, HIDN, 0, 0,
                           v16, nullptr, HIDN, 0, 0, bv, nullptr, nullptr, HIDN);
    dim3 gR(HIDN / BN, PROWS / BM);
    gemm16<1><<<gR, 256>>>(pe16, HIDN, 0, 0, wr16, HIDN, 0, 0,
                           r16, nullptr, HIDN, 0, 0, br, nullptr, nullptr, HIDN);

    // 3. transpose V for PV
    transpose_v<<<dim3(LLEN / 64, NBH), 256>>>();

    // 4. A-scores: (q+u) . k^T  -> att fp32 [bh,384,384]
    dim3 gA(LLEN / BN, LLEN / BM, NBH);
    gemm16<3><<<gA, 256>>>(qu, HIDN, MB, 64, k16, HIDN, MB, 64,
                           att, nullptr, LLEN, 8 * ATT, ATT,
                           nullptr, nullptr, nullptr, DHEAD);

    // 5. S: (q+vb) . rW_h^T  -> S fp32 [bh,384,768]
    dim3 gS(PROWS / BN, LLEN / BM, NBH);
    gemm16<3><<<gS, 256>>>(qv, HIDN, MB, 64, r16, HIDN, 0, 64,
                           S, nullptr, PROWS, 8 * SST, SST,
                           nullptr, nullptr, nullptr, DHEAD);

    // 6. softmax -> fp16 probs
    softmax_kernel<<<dim3(LLEN, NBH), 128>>>(seqlen);

    // 7. PV: P @ vT^T -> ctx fp16 [b,i,512]
    dim3 gPV(1, LLEN / BM, NBH);
    gemm16<4><<<gPV, 256>>>(p16, LLEN, 8 * ATT, ATT, vT, LLEN,
                            8 * (size_t)(DHEAD * LLEN), (size_t)(DHEAD * LLEN),
                            ctx16, nullptr, HIDN, MB, 64,
                            nullptr, nullptr, nullptr, LLEN);

    // 8. final projection -> fp32 out
    gemm16<0><<<gP, 256>>>(ctx16, HIDN, 0, 0, wf16, HIDN, 0, 0,
                           out, nullptr, HIDN, 0, 0, bf, nullptr, nullptr, HIDN);
}

// round 4
// speedup vs baseline: 3.6472x; 1.2435x over previous
#include <cuda_runtime.h>
#include <cuda_fp16.h>
#include <math.h>

// Problem constants
#define BB    8
#define LLEN  384
#define HIDN  512
#define NHEAD 8
#define DHEAD 64
#define PROWS 768
#define NBH   (BB*NHEAD)

// GEMM tile config
#define BM 128
#define BN 64
#define BK 32
#define PAD 40   // smem row stride in halves

// ---------------------------------------------------------------------------
// Scratch (device globals)
// ---------------------------------------------------------------------------
__device__ __half g_xk[BB*LLEN*HIDN];
__device__ __half g_xq[BB*LLEN*HIDN];
__device__ __half g_xv[BB*LLEN*HIDN];
__device__ __half g_pe16[PROWS*HIDN];
__device__ __half g_wq16[HIDN*HIDN];
__device__ __half g_wk16[HIDN*HIDN];
__device__ __half g_wv16[HIDN*HIDN];
__device__ __half g_wr16[HIDN*HIDN];
__device__ __half g_wf16[HIDN*HIDN];

__device__ __half g_qu[BB*LLEN*HIDN];    // 0.125*(q + bq + u_bias)
__device__ __half g_qv[BB*LLEN*HIDN];    // 0.125*(q + bq + v_bias)
__device__ __half g_k16[BB*LLEN*HIDN];
__device__ __half g_v16[BB*LLEN*HIDN];
__device__ __half g_r16[PROWS*HIDN];     // pe @ Wr^T + br
__device__ __half g_vT[NBH*DHEAD*LLEN];  // v transposed per (b,h): [d][j]
__device__ __half g_ctx16[BB*LLEN*HIDN];

__device__ __half g_A16[NBH*LLEN*LLEN];  // scaled A scores -> probs (in place)
__device__ __half g_S16[NBH*LLEN*PROWS]; // scaled shifted-rel scores

// ---------------------------------------------------------------------------
// fp32 -> fp16 convert
// ---------------------------------------------------------------------------
struct CvtArgs {
    const float* src[9];
    __half*      dst[9];
    int          n[9];
};

__global__ __launch_bounds__(256) void cvt_kernel(CvtArgs a) {
    int ti = blockIdx.y;
    int n  = a.n[ti];
    int i  = (blockIdx.x * 256 + threadIdx.x) * 8;
    if (i >= n) return;
    const float4* s = (const float4*)(a.src[ti] + i);
    float4 x = s[0], y = s[1];
    __half2 h0 = __floats2half2_rn(x.x, x.y);
    __half2 h1 = __floats2half2_rn(x.z, x.w);
    __half2 h2 = __floats2half2_rn(y.x, y.y);
    __half2 h3 = __floats2half2_rn(y.z, y.w);
    uint4 o;
    o.x = *(unsigned*)&h0; o.y = *(unsigned*)&h1;
    o.z = *(unsigned*)&h2; o.w = *(unsigned*)&h3;
    *(uint4*)(a.dst[ti] + i) = o;
}

// ---------------------------------------------------------------------------
// mma + cp.async helpers
// ---------------------------------------------------------------------------
__device__ __forceinline__ void mma16816(float* c, const unsigned* a, const unsigned* b) {
    asm volatile(
        "mma.sync.aligned.m16n8k16.row.col.f32.f16.f16.f32 "
        "{%0,%1,%2,%3}, {%4,%5,%6,%7}, {%8,%9}, {%0,%1,%2,%3};\n"
        : "+f"(c[0]), "+f"(c[1]), "+f"(c[2]), "+f"(c[3])
        : "r"(a[0]), "r"(a[1]), "r"(a[2]), "r"(a[3]), "r"(b[0]), "r"(b[1]));
}

__device__ __forceinline__ void cp16(__half* smem, const __half* gmem) {
    unsigned sa = (unsigned)__cvta_generic_to_shared(smem);
    asm volatile("cp.async.ca.shared.global [%0], [%1], 16;\n" :: "r"(sa), "l"(gmem));
}
#define CP_COMMIT() asm volatile("cp.async.commit_group;\n")
#define CP_WAIT0()  asm volatile("cp.async.wait_group 0;\n")

// ---------------------------------------------------------------------------
// Shared GEMM core: C_tile[128,64] += A[M,K] @ B[N,K]^T for one (m0,n0) tile.
// 256 threads (8 warps 4x2), double-buffered smem, cp.async fills.
// ---------------------------------------------------------------------------
__device__ __forceinline__ void gemm_tile(
    const __half* __restrict__ Ag, const __half* __restrict__ Ag2,
    const __half* __restrict__ Bg, int nk,
    __half* As, __half* Bs, float acc[2][4][4])
{
    const int t    = threadIdx.x;
    const int arow = t >> 2, achk = t & 3;
    const int warp = t >> 5, lane = t & 31;
    const int wm   = warp >> 1, wn = warp & 1;
    const int g    = lane >> 2, tg = lane & 3;

    __half* a0p = As + arow * PAD + achk * 8;
    __half* a1p = As + (arow + 64) * PAD + achk * 8;
    __half* b0p = Bs + arow * PAD + achk * 8;

    cp16(a0p, Ag); cp16(a1p, Ag2); cp16(b0p, Bg);
    CP_COMMIT(); CP_WAIT0();
    __syncthreads();

    for (int kt = 0; kt < nk; kt++) {
        const int cur = kt & 1;
        if (kt + 1 < nk) {
            const int nb = cur ^ 1;
            cp16(a0p + nb * BM * PAD, Ag  + (size_t)(kt + 1) * BK);
            cp16(a1p + nb * BM * PAD, Ag2 + (size_t)(kt + 1) * BK);
            cp16(b0p + nb * BN * PAD, Bg  + (size_t)(kt + 1) * BK);
            CP_COMMIT();
        }
        const __half* Ac = As + cur * BM * PAD;
        const __half* Bc = Bs + cur * BN * PAD;
#pragma unroll
        for (int ks = 0; ks < 2; ks++) {
            const int k0 = ks * 16;
            unsigned af[2][4], bf[4][2];
#pragma unroll
            for (int mi = 0; mi < 2; mi++) {
                const __half* base = Ac + (wm * 32 + mi * 16 + g) * PAD + k0 + tg * 2;
                af[mi][0] = *(const unsigned*)base;
                af[mi][1] = *(const unsigned*)(base + 8 * PAD);
                af[mi][2] = *(const unsigned*)(base + 8);
                af[mi][3] = *(const unsigned*)(base + 8 * PAD + 8);
            }
#pragma unroll
            for (int ni = 0; ni < 4; ni++) {
                const __half* base = Bc + (wn * 32 + ni * 8 + g) * PAD + k0 + tg * 2;
                bf[ni][0] = *(const unsigned*)base;
                bf[ni][1] = *(const unsigned*)(base + 8);
            }
#pragma unroll
            for (int mi = 0; mi < 2; mi++)
#pragma unroll
                for (int ni = 0; ni < 4; ni++)
                    mma16816(acc[mi][ni], af[mi], bf[ni]);
        }
        if (kt + 1 < nk) {
            CP_WAIT0();
            __syncthreads();
        }
    }
}

// ---------------------------------------------------------------------------
// Merged projection GEMM.  z selects job from a table.
// epi: 0 = dual fp16 (0.125*(acc+bias+ub), 0.125*(acc+bias+vb))
//      1 = fp16 + bias
//      2 = fp32 + bias
// All jobs: lda=ldb=ldc=512, K=512.
// ---------------------------------------------------------------------------
struct ProjArgs {
    const __half* A[4];
    const __half* B[4];
    void*         C0[4];
    void*         C1[4];
    const float*  bias[4];
    const float*  ub;
    const float*  vb;
    int           mtiles[4];
    int           epi[4];
};

__global__ __launch_bounds__(256) void proj_kernel(ProjArgs pa) {
    const int z = blockIdx.z;
    if ((int)blockIdx.y >= pa.mtiles[z]) return;

    __shared__ __align__(16) __half As[2 * BM * PAD];
    __shared__ __align__(16) __half Bs[2 * BN * PAD];

    const int t    = threadIdx.x;
    const int m0   = blockIdx.y * BM;
    const int n0   = blockIdx.x * BN;
    const int arow = t >> 2, achk = t & 3;
    const int warp = t >> 5, lane = t & 31;
    const int wm   = warp >> 1, wn = warp & 1;
    const int g    = lane >> 2, tg = lane & 3;

    const __half* A = pa.A[z];
    const __half* Bm = pa.B[z];
    const __half* Ag  = A + (size_t)(m0 + arow) * HIDN + achk * 8;
    const __half* Ag2 = A + (size_t)(m0 + arow + 64) * HIDN + achk * 8;
    const __half* Bg  = Bm + (size_t)(n0 + arow) * HIDN + achk * 8;

    float acc[2][4][4];
#pragma unroll
    for (int mi = 0; mi < 2; mi++)
#pragma unroll
        for (int ni = 0; ni < 4; ni++)
#pragma unroll
            for (int u = 0; u < 4; u++) acc[mi][ni][u] = 0.f;

    gemm_tile(Ag, Ag2, Bg, HIDN / BK, As, Bs, acc);

    const int epi = pa.epi[z];
    const float* bias = pa.bias[z];
#pragma unroll
    for (int mi = 0; mi < 2; mi++) {
        const int r0 = m0 + wm * 32 + mi * 16 + g;
#pragma unroll
        for (int ni = 0; ni < 4; ni++) {
            const int cb = n0 + wn * 32 + ni * 8 + tg * 2;
            float* ac = acc[mi][ni];
            const size_t o0 = (size_t)r0 * HIDN + cb;
            const size_t o1 = (size_t)(r0 + 8) * HIDN + cb;
            const float b0 = bias[cb], b1 = bias[cb + 1];
            if (epi == 0) {
                const float u0 = 0.125f * (ac[0] + b0 + pa.ub[cb]);
                const float u1 = 0.125f * (ac[1] + b1 + pa.ub[cb + 1]);
                const float u2 = 0.125f * (ac[2] + b0 + pa.ub[cb]);
                const float u3 = 0.125f * (ac[3] + b1 + pa.ub[cb + 1]);
                const float v0 = 0.125f * (ac[0] + b0 + pa.vb[cb]);
                const float v1 = 0.125f * (ac[1] + b1 + pa.vb[cb + 1]);
                const float v2 = 0.125f * (ac[2] + b0 + pa.vb[cb]);
                const float v3 = 0.125f * (ac[3] + b1 + pa.vb[cb + 1]);
                *(__half2*)((__half*)pa.C0[z] + o0) = __floats2half2_rn(u0, u1);
                *(__half2*)((__half*)pa.C0[z] + o1) = __floats2half2_rn(u2, u3);
                *(__half2*)((__half*)pa.C1[z] + o0) = __floats2half2_rn(v0, v1);
                *(__half2*)((__half*)pa.C1[z] + o1) = __floats2half2_rn(v2, v3);
            } else if (epi == 1) {
                *(__half2*)((__half*)pa.C0[z] + o0) = __floats2half2_rn(ac[0] + b0, ac[1] + b1);
                *(__half2*)((__half*)pa.C0[z] + o1) = __floats2half2_rn(ac[2] + b0, ac[3] + b1);
            } else {
                *(float2*)((float*)pa.C0[z] + o0) = make_float2(ac[0] + b0, ac[1] + b1);
                *(float2*)((float*)pa.C0[z] + o1) = make_float2(ac[2] + b0, ac[3] + b1);
            }
        }
    }
}

// ---------------------------------------------------------------------------
// Merged score GEMM: z in [0,128): job = z>>6 (0 = A-scores, 1 = S), bh = z&63.
// A-scores: C[bh][i][j] = qu . k      (N=384, x<6)
// S:        C[bh][i][p] = qv . rW_h   (N=768, x<12)
// K = 64, fp16 raw output.
// ---------------------------------------------------------------------------
__global__ __launch_bounds__(256) void score_kernel() {
    const int z   = blockIdx.z;
    const int job = z >> 6;
    const int bh  = z & 63;
    if (job == 0 && blockIdx.x >= LLEN / BN) return;
    const int b = bh >> 3, h = bh & 7;

    __shared__ __align__(16) __half As[2 * BM * PAD];
    __shared__ __align__(16) __half Bs[2 * BN * PAD];

    const int t    = threadIdx.x;
    const int m0   = blockIdx.y * BM;
    const int n0   = blockIdx.x * BN;
    const int arow = t >> 2, achk = t & 3;
    const int warp = t >> 5, lane = t & 31;
    const int wm   = warp >> 1, wn = warp & 1;
    const int g    = lane >> 2, tg = lane & 3;

    const size_t MB = (size_t)LLEN * HIDN;
    const __half* A = (job ? g_qv : g_qu) + (size_t)b * MB + h * DHEAD;
    const __half* Bm = job ? (g_r16 + h * DHEAD) : (g_k16 + (size_t)b * MB + h * DHEAD);
    __half* C   = job ? (g_S16 + (size_t)bh * LLEN * PROWS)
                      : (g_A16 + (size_t)bh * LLEN * LLEN);
    const int ldc = job ? PROWS : LLEN;

    const __half* Ag  = A + (size_t)(m0 + arow) * HIDN + achk * 8;
    const __half* Ag2 = A + (size_t)(m0 + arow + 64) * HIDN + achk * 8;
    const __half* Bg  = Bm + (size_t)(n0 + arow) * HIDN + achk * 8;

    float acc[2][4][4];
#pragma unroll
    for (int mi = 0; mi < 2; mi++)
#pragma unroll
        for (int ni = 0; ni < 4; ni++)
#pragma unroll
            for (int u = 0; u < 4; u++) acc[mi][ni][u] = 0.f;

    gemm_tile(Ag, Ag2, Bg, DHEAD / BK, As, Bs, acc);

#pragma unroll
    for (int mi = 0; mi < 2; mi++) {
        const int r0 = m0 + wm * 32 + mi * 16 + g;
#pragma unroll
        for (int ni = 0; ni < 4; ni++) {
            const int cb = n0 + wn * 32 + ni * 8 + tg * 2;
            float* ac = acc[mi][ni];
            *(__half2*)(C + (size_t)r0 * ldc + cb)       = __floats2half2_rn(ac[0], ac[1]);
            *(__half2*)(C + (size_t)(r0 + 8) * ldc + cb) = __floats2half2_rn(ac[2], ac[3]);
        }
    }
}

// ---------------------------------------------------------------------------
// PV GEMM: ctx[b,i,h*64+d] = sum_j P[bh,i,j] * vT[bh,d,j]   (K=384)
// ---------------------------------------------------------------------------
__global__ __launch_bounds__(256) void pv_kernel() {
    const int bh = blockIdx.z;
    const int b = bh >> 3, h = bh & 7;

    __shared__ __align__(16) __half As[2 * BM * PAD];
    __shared__ __align__(16) __half Bs[2 * BN * PAD];

    const int t    = threadIdx.x;
    const int m0   = blockIdx.y * BM;
    const int arow = t >> 2, achk = t & 3;
    const int warp = t >> 5, lane = t & 31;
    const int wm   = warp >> 1, wn = warp & 1;
    const int g    = lane >> 2, tg = lane & 3;

    const __half* A = g_A16 + (size_t)bh * LLEN * LLEN;   // probs (in-place)
    const __half* Bm = g_vT + (size_t)bh * DHEAD * LLEN;

    const __half* Ag  = A + (size_t)(m0 + arow) * LLEN + achk * 8;
    const __half* Ag2 = A + (size_t)(m0 + arow + 64) * LLEN + achk * 8;
    const __half* Bg  = Bm + (size_t)arow * LLEN + achk * 8;

    float acc[2][4][4];
#pragma unroll
    for (int mi = 0; mi < 2; mi++)
#pragma unroll
        for (int ni = 0; ni < 4; ni++)
#pragma unroll
            for (int u = 0; u < 4; u++) acc[mi][ni][u] = 0.f;

    gemm_tile(Ag, Ag2, Bg, LLEN / BK, As, Bs, acc);

    __half* Cb = g_ctx16 + (size_t)b * LLEN * HIDN + h * DHEAD;
#pragma unroll
    for (int mi = 0; mi < 2; mi++) {
        const int r0 = m0 + wm * 32 + mi * 16 + g;
#pragma unroll
        for (int ni = 0; ni < 4; ni++) {
            const int cb = wn * 32 + ni * 8 + tg * 2;
            float* ac = acc[mi][ni];
            *(__half2*)(Cb + (size_t)r0 * HIDN + cb)       = __floats2half2_rn(ac[0], ac[1]);
            *(__half2*)(Cb + (size_t)(r0 + 8) * HIDN + cb) = __floats2half2_rn(ac[2], ac[3]);
        }
    }
}

// ---------------------------------------------------------------------------
// Transpose V per (b,h): vT[bh][d][j] = v16[b*384+j][h*64+d]
// ---------------------------------------------------------------------------
__global__ __launch_bounds__(256) void transpose_v() {
    __shared__ __half tile[64][72];
    const int z = blockIdx.y, b = z >> 3, h = z & 7;
    const int j0 = blockIdx.x * 64;
    const int t = threadIdx.x;
#pragma unroll
    for (int it = 0; it < 2; it++) {
        int idx = t + it * 256;
        int j = idx >> 3, ch = idx & 7;
        uint4 val = *(const uint4*)(g_v16 + (size_t)(b * LLEN + j0 + j) * HIDN + h * 64 + ch * 8);
        *(uint4*)&tile[j][ch * 8] = val;
    }
    __syncthreads();
#pragma unroll
    for (int it = 0; it < 2; it++) {
        int idx = t + it * 256;
        int d = idx >> 3, ch = idx & 7;
        __half tmp[8];
#pragma unroll
        for (int u = 0; u < 8; u++) tmp[u] = tile[ch * 8 + u][d];
        *(uint4*)(g_vT + (size_t)(z * 64 + d) * LLEN + j0 + ch * 8) = *(uint4*)tmp;
    }
}

// ---------------------------------------------------------------------------
// Fused combine + rel-shift gather + mask + softmax (in place over g_A16).
// Scores already carry the 1/8 scale (folded into qu/qv).
// ---------------------------------------------------------------------------
__global__ __launch_bounds__(128) void softmax_kernel(const int* __restrict__ seq_len) {
    __shared__ float red[128];
    const int i  = blockIdx.x;
    const int bh = blockIdx.y;
    const int b  = bh >> 3;
    const int sl = seq_len[b];
    const int t  = threadIdx.x;

    __half* Arow       = g_A16 + ((size_t)bh * LLEN + i) * LLEN;
    const __half* Srow = g_S16 + ((size_t)bh * LLEN + i) * PROWS + (LLEN - i);

    float x[3];
    float mx = -3.0e38f;
#pragma unroll
    for (int c = 0; c < 3; c++) {
        int j = t + c * 128;
        float v = (j < sl) ? (__half2float(Arow[j]) + __half2float(Srow[j])) : -3.0e38f;
        x[c] = v;
        mx = fmaxf(mx, v);
    }
    red[t] = mx; __syncthreads();
    for (int s = 64; s > 0; s >>= 1) {
        if (t < s) red[t] = fmaxf(red[t], red[t + s]);
        __syncthreads();
    }
    mx = red[0]; __syncthreads();

    float p[3];
    float sum = 0.f;
#pragma unroll
    for (int c = 0; c < 3; c++) {
        int j = t + c * 128;
        p[c] = (j < sl) ? __expf(x[c] - mx) : 0.f;
        sum += p[c];
    }
    red[t] = sum; __syncthreads();
    for (int s = 64; s > 0; s >>= 1) {
        if (t < s) red[t] += red[t + s];
        __syncthreads();
    }
    const float inv = 1.f / red[0];
#pragma unroll
    for (int c = 0; c < 3; c++) {
        int j = t + c * 128;
        Arow[j] = __float2half(p[c] * inv);
    }
}

// ---------------------------------------------------------------------------
// Launcher
// ---------------------------------------------------------------------------
extern "C" void kernel_launch(void* const* d_in, const int* in_sizes, int n_in,
                              void* d_out, int out_size) {
    const float* key    = (const float*)d_in[0];
    const float* query  = (const float*)d_in[1];
    const float* value  = (const float*)d_in[2];
    const int*   seqlen = (const int*)  d_in[3];
    const float* pe     = (const float*)d_in[4];
    const float* Wk = (const float*)d_in[5],  *bk = (const float*)d_in[6];
    const float* Wq = (const float*)d_in[7],  *bq = (const float*)d_in[8];
    const float* Wv = (const float*)d_in[9],  *bv = (const float*)d_in[10];
    const float* Wr = (const float*)d_in[11], *br = (const float*)d_in[12];
    const float* u_bias = (const float*)d_in[13];
    const float* v_bias = (const float*)d_in[14];
    const float* Wf = (const float*)d_in[15], *bf = (const float*)d_in[16];
    float* out = (float*)d_out;

    __half *xk, *xq, *xv, *pe16, *wq16, *wk16, *wv16, *wr16, *wf16;
    __half *qu, *qv, *k16, *v16, *r16, *ctx16;
    cudaGetSymbolAddress((void**)&xk,   g_xk);
    cudaGetSymbolAddress((void**)&xq,   g_xq);
    cudaGetSymbolAddress((void**)&xv,   g_xv);
    cudaGetSymbolAddress((void**)&pe16, g_pe16);
    cudaGetSymbolAddress((void**)&wq16, g_wq16);
    cudaGetSymbolAddress((void**)&wk16, g_wk16);
    cudaGetSymbolAddress((void**)&wv16, g_wv16);
    cudaGetSymbolAddress((void**)&wr16, g_wr16);
    cudaGetSymbolAddress((void**)&wf16, g_wf16);
    cudaGetSymbolAddress((void**)&qu,   g_qu);
    cudaGetSymbolAddress((void**)&qv,   g_qv);
    cudaGetSymbolAddress((void**)&k16,  g_k16);
    cudaGetSymbolAddress((void**)&v16,  g_v16);
    cudaGetSymbolAddress((void**)&r16,  g_r16);
    cudaGetSymbolAddress((void**)&ctx16,g_ctx16);

    // 1. convert everything to fp16
    CvtArgs ca;
    ca.src[0] = key;   ca.dst[0] = xk;   ca.n[0] = BB*LLEN*HIDN;
    ca.src[1] = query; ca.dst[1] = xq;   ca.n[1] = BB*LLEN*HIDN;
    ca.src[2] = value; ca.dst[2] = xv;   ca.n[2] = BB*LLEN*HIDN;
    ca.src[3] = pe;    ca.dst[3] = pe16; ca.n[3] = PROWS*HIDN;
    ca.src[4] = Wq;    ca.dst[4] = wq16; ca.n[4] = HIDN*HIDN;
    ca.src[5] = Wk;    ca.dst[5] = wk16; ca.n[5] = HIDN*HIDN;
    ca.src[6] = Wv;    ca.dst[6] = wv16; ca.n[6] = HIDN*HIDN;
    ca.src[7] = Wr;    ca.dst[7] = wr16; ca.n[7] = HIDN*HIDN;
    ca.src[8] = Wf;    ca.dst[8] = wf16; ca.n[8] = HIDN*HIDN;
    cvt_kernel<<<dim3(768, 9), 256>>>(ca);

    // 2. merged projections: Q (dual, pre-scaled), K, V, R
    ProjArgs pj;
    pj.A[0] = xq;   pj.B[0] = wq16; pj.C0[0] = qu;  pj.C1[0] = qv;
    pj.bias[0] = bq; pj.mtiles[0] = 24; pj.epi[0] = 0;
    pj.A[1] = xk;   pj.B[1] = wk16; pj.C0[1] = k16; pj.C1[1] = nullptr;
    pj.bias[1] = bk; pj.mtiles[1] = 24; pj.epi[1] = 1;
    pj.A[2] = xv;   pj.B[2] = wv16; pj.C0[2] = v16; pj.C1[2] = nullptr;
    pj.bias[2] = bv; pj.mtiles[2] = 24; pj.epi[2] = 1;
    pj.A[3] = pe16; pj.B[3] = wr16; pj.C0[3] = r16; pj.C1[3] = nullptr;
    pj.bias[3] = br; pj.mtiles[3] = 6;  pj.epi[3] = 1;
    pj.ub = u_bias; pj.vb = v_bias;
    proj_kernel<<<dim3(HIDN / BN, 24, 4), 256>>>(pj);

    // 3. transpose V
    transpose_v<<<dim3(LLEN / 64, NBH), 256>>>();

    // 4. merged scores: A (z<64) + S (z>=64), fp16 outputs
    score_kernel<<<dim3(PROWS / BN, LLEN / BM, 128), 256>>>();

    // 5. softmax in place (A16 -> probs)
    softmax_kernel<<<dim3(LLEN, NBH), 128>>>(seqlen);

    // 6. PV -> ctx16
    pv_kernel<<<dim3(1, LLEN / BM, NBH), 256>>>();

    // 7. final projection -> fp32 out
    ProjArgs pf;
    pf.A[0] = ctx16; pf.B[0] = wf16; pf.C0[0] = out; pf.C1[0] = nullptr;
    pf.bias[0] = bf; pf.mtiles[0] = 24; pf.epi[0] = 2;
    pf.ub = nullptr; pf.vb = nullptr;
    pf.A[1] = pf.A[2] = pf.A[3] = nullptr;
    pf.B[1] = pf.B[2] = pf.B[3] = nullptr;
    pf.C0[1] = pf.C0[2] = pf.C0[3] = nullptr;
    pf.C1[1] = pf.C1[2] = pf.C1[3] = nullptr;
    pf.bias[1] = pf.bias[2] = pf.bias[3] = nullptr;
    pf.mtiles[1] = pf.mtiles[2] = pf.mtiles[3] = 0;
    pf.epi[1] = pf.epi[2] = pf.epi[3] = 0;
    proj_kernel<<<dim3(HIDN / BN, 24, 1), 256>>>(pf);
}

// round 5
// speedup vs baseline: 4.1890x; 1.1486x over previous
#include <cuda_runtime.h>
#include <cuda_fp16.h>
#include <math.h>

// Problem constants
#define BB    8
#define LLEN  384
#define HIDN  512
#define NHEAD 8
#define DHEAD 64
#define PROWS 768
#define NBH   (BB*NHEAD)

// GEMM tile config (projection kernel)
#define BM 128
#define BN 64
#define BK 32
#define PAD 40   // smem row stride in halves

// fused softmax+PV
#define PSTR 392 // smem prob row stride in halves (392*2B=784B; 196 words %32 = 4 -> conflict-free)

// ---------------------------------------------------------------------------
// Scratch (device globals)
// ---------------------------------------------------------------------------
__device__ __half g_xk[BB*LLEN*HIDN];
__device__ __half g_xq[BB*LLEN*HIDN];
__device__ __half g_xv[BB*LLEN*HIDN];
__device__ __half g_pe16[PROWS*HIDN];
__device__ __half g_wq16[HIDN*HIDN];
__device__ __half g_wk16[HIDN*HIDN];
__device__ __half g_wv16[HIDN*HIDN];
__device__ __half g_wr16[HIDN*HIDN];
__device__ __half g_wf16[HIDN*HIDN];

__device__ __half g_qu[BB*LLEN*HIDN];    // 0.125*(q + bq + u_bias)
__device__ __half g_qv[BB*LLEN*HIDN];    // 0.125*(q + bq + v_bias)
__device__ __half g_k16[BB*LLEN*HIDN];
__device__ __half g_v16[BB*LLEN*HIDN];
__device__ __half g_r16[PROWS*HIDN];     // pe @ Wr^T + br
__device__ __half g_vT[NBH*DHEAD*LLEN];  // v transposed per (b,h): [d][j]
__device__ __half g_ctx16[BB*LLEN*HIDN];

__device__ __half g_A16[NBH*LLEN*LLEN];  // scaled A scores
__device__ __half g_S16[NBH*LLEN*PROWS]; // scaled shifted-rel scores

// ---------------------------------------------------------------------------
// fp32 -> fp16 convert
// ---------------------------------------------------------------------------
struct CvtArgs {
    const float* src[9];
    __half*      dst[9];
    int          n[9];
};

__global__ __launch_bounds__(256) void cvt_kernel(CvtArgs a) {
    int ti = blockIdx.y;
    int n  = a.n[ti];
    int i  = (blockIdx.x * 256 + threadIdx.x) * 8;
    if (i >= n) return;
    const float4* s = (const float4*)(a.src[ti] + i);
    float4 x = s[0], y = s[1];
    __half2 h0 = __floats2half2_rn(x.x, x.y);
    __half2 h1 = __floats2half2_rn(x.z, x.w);
    __half2 h2 = __floats2half2_rn(y.x, y.y);
    __half2 h3 = __floats2half2_rn(y.z, y.w);
    uint4 o;
    o.x = *(unsigned*)&h0; o.y = *(unsigned*)&h1;
    o.z = *(unsigned*)&h2; o.w = *(unsigned*)&h3;
    *(uint4*)(a.dst[ti] + i) = o;
}

// ---------------------------------------------------------------------------
// mma + cp.async helpers
// ---------------------------------------------------------------------------
__device__ __forceinline__ void mma16816(float* c, const unsigned* a, const unsigned* b) {
    asm volatile(
        "mma.sync.aligned.m16n8k16.row.col.f32.f16.f16.f32 "
        "{%0,%1,%2,%3}, {%4,%5,%6,%7}, {%8,%9}, {%0,%1,%2,%3};\n"
        : "+f"(c[0]), "+f"(c[1]), "+f"(c[2]), "+f"(c[3])
        : "r"(a[0]), "r"(a[1]), "r"(a[2]), "r"(a[3]), "r"(b[0]), "r"(b[1]));
}

__device__ __forceinline__ void cp16(__half* smem, const __half* gmem) {
    unsigned sa = (unsigned)__cvta_generic_to_shared(smem);
    asm volatile("cp.async.ca.shared.global [%0], [%1], 16;\n" :: "r"(sa), "l"(gmem));
}
#define CP_COMMIT() asm volatile("cp.async.commit_group;\n")
#define CP_WAIT0()  asm volatile("cp.async.wait_group 0;\n")

// ---------------------------------------------------------------------------
// Shared GEMM core for projection kernel (unchanged from R3)
// ---------------------------------------------------------------------------
__device__ __forceinline__ void gemm_tile(
    const __half* __restrict__ Ag, const __half* __restrict__ Ag2,
    const __half* __restrict__ Bg, int nk,
    __half* As, __half* Bs, float acc[2][4][4])
{
    const int t    = threadIdx.x;
    const int arow = t >> 2, achk = t & 3;
    const int warp = t >> 5, lane = t & 31;
    const int wm   = warp >> 1, wn = warp & 1;
    const int g    = lane >> 2, tg = lane & 3;

    __half* a0p = As + arow * PAD + achk * 8;
    __half* a1p = As + (arow + 64) * PAD + achk * 8;
    __half* b0p = Bs + arow * PAD + achk * 8;

    cp16(a0p, Ag); cp16(a1p, Ag2); cp16(b0p, Bg);
    CP_COMMIT(); CP_WAIT0();
    __syncthreads();

    for (int kt = 0; kt < nk; kt++) {
        const int cur = kt & 1;
        if (kt + 1 < nk) {
            const int nb = cur ^ 1;
            cp16(a0p + nb * BM * PAD, Ag  + (size_t)(kt + 1) * BK);
            cp16(a1p + nb * BM * PAD, Ag2 + (size_t)(kt + 1) * BK);
            cp16(b0p + nb * BN * PAD, Bg  + (size_t)(kt + 1) * BK);
            CP_COMMIT();
        }
        const __half* Ac = As + cur * BM * PAD;
        const __half* Bc = Bs + cur * BN * PAD;
#pragma unroll
        for (int ks = 0; ks < 2; ks++) {
            const int k0 = ks * 16;
            unsigned af[2][4], bf[4][2];
#pragma unroll
            for (int mi = 0; mi < 2; mi++) {
                const __half* base = Ac + (wm * 32 + mi * 16 + g) * PAD + k0 + tg * 2;
                af[mi][0] = *(const unsigned*)base;
                af[mi][1] = *(const unsigned*)(base + 8 * PAD);
                af[mi][2] = *(const unsigned*)(base + 8);
                af[mi][3] = *(const unsigned*)(base + 8 * PAD + 8);
            }
#pragma unroll
            for (int ni = 0; ni < 4; ni++) {
                const __half* base = Bc + (wn * 32 + ni * 8 + g) * PAD + k0 + tg * 2;
                bf[ni][0] = *(const unsigned*)base;
                bf[ni][1] = *(const unsigned*)(base + 8);
            }
#pragma unroll
            for (int mi = 0; mi < 2; mi++)
#pragma unroll
                for (int ni = 0; ni < 4; ni++)
                    mma16816(acc[mi][ni], af[mi], bf[ni]);
        }
        if (kt + 1 < nk) {
            CP_WAIT0();
            __syncthreads();
        }
    }
}

// ---------------------------------------------------------------------------
// Merged projection GEMM (Q dual / K / V / R, and final proj)
// ---------------------------------------------------------------------------
struct ProjArgs {
    const __half* A[4];
    const __half* B[4];
    void*         C0[4];
    void*         C1[4];
    const float*  bias[4];
    const float*  ub;
    const float*  vb;
    int           mtiles[4];
    int           epi[4];
};

__global__ __launch_bounds__(256) void proj_kernel(ProjArgs pa) {
    const int z = blockIdx.z;
    if ((int)blockIdx.y >= pa.mtiles[z]) return;

    __shared__ __align__(16) __half As[2 * BM * PAD];
    __shared__ __align__(16) __half Bs[2 * BN * PAD];

    const int t    = threadIdx.x;
    const int m0   = blockIdx.y * BM;
    const int n0   = blockIdx.x * BN;
    const int arow = t >> 2, achk = t & 3;
    const int warp = t >> 5, lane = t & 31;
    const int wm   = warp >> 1, wn = warp & 1;
    const int g    = lane >> 2, tg = lane & 3;

    const __half* A = pa.A[z];
    const __half* Bm = pa.B[z];
    const __half* Ag  = A + (size_t)(m0 + arow) * HIDN + achk * 8;
    const __half* Ag2 = A + (size_t)(m0 + arow + 64) * HIDN + achk * 8;
    const __half* Bg  = Bm + (size_t)(n0 + arow) * HIDN + achk * 8;

    float acc[2][4][4];
#pragma unroll
    for (int mi = 0; mi < 2; mi++)
#pragma unroll
        for (int ni = 0; ni < 4; ni++)
#pragma unroll
            for (int u = 0; u < 4; u++) acc[mi][ni][u] = 0.f;

    gemm_tile(Ag, Ag2, Bg, HIDN / BK, As, Bs, acc);

    const int epi = pa.epi[z];
    const float* bias = pa.bias[z];
#pragma unroll
    for (int mi = 0; mi < 2; mi++) {
        const int r0 = m0 + wm * 32 + mi * 16 + g;
#pragma unroll
        for (int ni = 0; ni < 4; ni++) {
            const int cb = n0 + wn * 32 + ni * 8 + tg * 2;
            float* ac = acc[mi][ni];
            const size_t o0 = (size_t)r0 * HIDN + cb;
            const size_t o1 = (size_t)(r0 + 8) * HIDN + cb;
            const float b0 = bias[cb], b1 = bias[cb + 1];
            if (epi == 0) {
                const float u0 = 0.125f * (ac[0] + b0 + pa.ub[cb]);
                const float u1 = 0.125f * (ac[1] + b1 + pa.ub[cb + 1]);
                const float u2 = 0.125f * (ac[2] + b0 + pa.ub[cb]);
                const float u3 = 0.125f * (ac[3] + b1 + pa.ub[cb + 1]);
                const float v0 = 0.125f * (ac[0] + b0 + pa.vb[cb]);
                const float v1 = 0.125f * (ac[1] + b1 + pa.vb[cb + 1]);
                const float v2 = 0.125f * (ac[2] + b0 + pa.vb[cb]);
                const float v3 = 0.125f * (ac[3] + b1 + pa.vb[cb + 1]);
                *(__half2*)((__half*)pa.C0[z] + o0) = __floats2half2_rn(u0, u1);
                *(__half2*)((__half*)pa.C0[z] + o1) = __floats2half2_rn(u2, u3);
                *(__half2*)((__half*)pa.C1[z] + o0) = __floats2half2_rn(v0, v1);
                *(__half2*)((__half*)pa.C1[z] + o1) = __floats2half2_rn(v2, v3);
            } else if (epi == 1) {
                *(__half2*)((__half*)pa.C0[z] + o0) = __floats2half2_rn(ac[0] + b0, ac[1] + b1);
                *(__half2*)((__half*)pa.C0[z] + o1) = __floats2half2_rn(ac[2] + b0, ac[3] + b1);
            } else {
                *(float2*)((float*)pa.C0[z] + o0) = make_float2(ac[0] + b0, ac[1] + b1);
                *(float2*)((float*)pa.C0[z] + o1) = make_float2(ac[2] + b0, ac[3] + b1);
            }
        }
    }
}

// ---------------------------------------------------------------------------
// Score kernel v2: A-stationary.
// blockIdx.x = mtile (3), blockIdx.y = z in [0,128): job=z>>6, bh=z&63.
// job 0: A[bh][i][j] = qu . k     (N=384)
// job 1: S[bh][i][p] = qv . rW_h  (N=768)
// Loads 128x64 A tile once, keeps all mma A-fragments in registers,
// sweeps n-tiles double-buffering only B.
// ---------------------------------------------------------------------------
#define ASTR 72  // A smem stride (halves): 36 words %32 = 4 -> conflict-free

__global__ __launch_bounds__(256) void score_kernel() {
    const int z   = blockIdx.y;
    const int job = z >> 6;
    const int bh  = z & 63;
    const int b   = bh >> 3, h = bh & 7;

    __shared__ __align__(16) __half As2[128 * ASTR];          // 18432 B
    __shared__ __align__(16) __half Bs[2][2][64 * PAD];        // 20480 B

    const int t    = threadIdx.x;
    const int m0   = blockIdx.x * 128;
    const int warp = t >> 5, lane = t & 31;
    const int wm   = warp >> 1, wn = warp & 1;
    const int g    = lane >> 2, tg = lane & 3;

    const size_t MB = (size_t)LLEN * HIDN;
    const __half* A  = (job ? g_qv : g_qu) + (size_t)b * MB + h * DHEAD;
    const __half* Bm = job ? (g_r16 + h * DHEAD) : (g_k16 + (size_t)b * MB + h * DHEAD);
    __half* C  = job ? (g_S16 + (size_t)bh * LLEN * PROWS)
                     : (g_A16 + (size_t)bh * LLEN * LLEN);
    const int N   = job ? PROWS : LLEN;
    const int ldc = N;
    const int ntiles = N / 64;

    // ---- load A tile (128 x 64 halves) ----
#pragma unroll
    for (int p = 0; p < 4; p++) {
        int idx = t + p * 256;
        int row = idx >> 3, col = (idx & 7) * 8;
        cp16(&As2[row * ASTR + col], A + (size_t)(m0 + row) * HIDN + col);
    }
    // ---- load first B tile (both 32-k chunks) ----
    {
        int row = t >> 2, kc = (t & 3) * 8;
#pragma unroll
        for (int c = 0; c < 2; c++)
            cp16(&Bs[0][c][row * PAD + kc], Bm + (size_t)row * HIDN + c * 32 + kc);
    }
    CP_COMMIT(); CP_WAIT0();
    __syncthreads();

    // ---- build A fragments in registers (K=64 -> 4 slices of 16) ----
    unsigned af[2][4][4];
#pragma unroll
    for (int mi = 0; mi < 2; mi++)
#pragma unroll
        for (int ks = 0; ks < 4; ks++) {
            const __half* base = &As2[(wm * 32 + mi * 16 + g) * ASTR + ks * 16 + tg * 2];
            af[mi][ks][0] = *(const unsigned*)base;
            af[mi][ks][1] = *(const unsigned*)(base + 8 * ASTR);
            af[mi][ks][2] = *(const unsigned*)(base + 8);
            af[mi][ks][3] = *(const unsigned*)(base + 8 * ASTR + 8);
        }

    for (int nt = 0; nt < ntiles; nt++) {
        const int stage = nt & 1;
        if (nt + 1 < ntiles) {
            int row = t >> 2, kc = (t & 3) * 8;
            const __half* Bn = Bm + (size_t)(nt + 1) * 64 * HIDN;
#pragma unroll
            for (int c = 0; c < 2; c++)
                cp16(&Bs[stage ^ 1][c][row * PAD + kc], Bn + (size_t)row * HIDN + c * 32 + kc);
            CP_COMMIT();
        }
        float acc[2][4][4];
#pragma unroll
        for (int mi = 0; mi < 2; mi++)
#pragma unroll
            for (int ni = 0; ni < 4; ni++)
#pragma unroll
                for (int u = 0; u < 4; u++) acc[mi][ni][u] = 0.f;

#pragma unroll
        for (int ks = 0; ks < 4; ks++) {
            const __half* Bc = Bs[stage][ks >> 1];
            const int k0 = (ks & 1) * 16;
            unsigned bf[4][2];
#pragma unroll
            for (int ni = 0; ni < 4; ni++) {
                const __half* base = Bc + (wn * 32 + ni * 8 + g) * PAD + k0 + tg * 2;
                bf[ni][0] = *(const unsigned*)base;
                bf[ni][1] = *(const unsigned*)(base + 8);
            }
#pragma unroll
            for (int mi = 0; mi < 2; mi++)
#pragma unroll
                for (int ni = 0; ni < 4; ni++)
                    mma16816(acc[mi][ni], af[mi][ks], bf[ni]);
        }

        // epilogue
        const int n0 = nt * 64;
#pragma unroll
        for (int mi = 0; mi < 2; mi++) {
            const int r0 = m0 + wm * 32 + mi * 16 + g;
#pragma unroll
            for (int ni = 0; ni < 4; ni++) {
                const int cb = n0 + wn * 32 + ni * 8 + tg * 2;
                float* ac = acc[mi][ni];
                *(__half2*)(C + (size_t)r0 * ldc + cb)       = __floats2half2_rn(ac[0], ac[1]);
                *(__half2*)(C + (size_t)(r0 + 8) * ldc + cb) = __floats2half2_rn(ac[2], ac[3]);
            }
        }
        if (nt + 1 < ntiles) {
            CP_WAIT0();
            __syncthreads();
        }
    }
}

// ---------------------------------------------------------------------------
// Fused softmax + PV.
// blockIdx.x = mtile (6, 64 rows each), blockIdx.y = bh.
// Phase 1: combine A16 + shifted S16, mask, softmax -> probs in smem.
// Phase 2: ctx[64,64] = P[64,384] @ vT[64,384]^T via mma, B double-buffered.
// Dynamic smem: P (64*PSTR halves) + Bs (2 * 64*PAD halves).
// ---------------------------------------------------------------------------
__global__ __launch_bounds__(256) void softpv_kernel(const int* __restrict__ seq_len) {
    extern __shared__ __align__(16) __half dyn[];
    __half* P  = dyn;                       // 64 * PSTR
    __half* Bs = dyn + 64 * PSTR;           // 2 * 64 * PAD

    const int t    = threadIdx.x;
    const int warp = t >> 5, lane = t & 31;
    const int bh   = blockIdx.y;
    const int b    = bh >> 3, h = bh & 7;
    const int m0   = blockIdx.x * 64;
    const int sl   = seq_len[b];

    const __half* Abase = g_A16 + (size_t)bh * LLEN * LLEN;
    const __half* Sbase = g_S16 + (size_t)bh * LLEN * PROWS;

    // ---- Phase 1: softmax (8 warps x 8 rows) ----
#pragma unroll 1
    for (int rr = 0; rr < 8; rr++) {
        const int lr = warp * 8 + rr;       // local row 0..63
        const int i  = m0 + lr;             // global row
        const __half* Arow = Abase + (size_t)i * LLEN;
        const __half* Srow = Sbase + (size_t)i * PROWS + (LLEN - i);

        float x[12];
        float mx = -3.0e38f;
#pragma unroll
        for (int s = 0; s < 12; s++) {
            const int j = lane + s * 32;
            float v = (j < sl) ? (__half2float(Arow[j]) + __half2float(Srow[j])) : -3.0e38f;
            x[s] = v;
            mx = fmaxf(mx, v);
        }
#pragma unroll
        for (int o = 16; o > 0; o >>= 1)
            mx = fmaxf(mx, __shfl_xor_sync(0xffffffffu, mx, o));
        float sum = 0.f;
#pragma unroll
        for (int s = 0; s < 12; s++) {
            const int j = lane + s * 32;
            x[s] = (j < sl) ? __expf(x[s] - mx) : 0.f;
            sum += x[s];
        }
#pragma unroll
        for (int o = 16; o > 0; o >>= 1)
            sum += __shfl_xor_sync(0xffffffffu, sum, o);
        const float inv = 1.f / sum;
#pragma unroll
        for (int s = 0; s < 12; s++)
            P[lr * PSTR + lane + s * 32] = __float2half(x[s] * inv);
    }
    __syncthreads();

    // ---- Phase 2: PV ----
    const int wm = warp >> 1, wn = warp & 1;
    const int g  = lane >> 2, tg = lane & 3;
    const __half* vTb = g_vT + (size_t)bh * DHEAD * LLEN;

    // prologue: B tile for kt=0
    {
        int row = t >> 2, kc = (t & 3) * 8;
        cp16(&Bs[row * PAD + kc], vTb + (size_t)row * LLEN + kc);
    }
    CP_COMMIT(); CP_WAIT0();
    __syncthreads();

    float acc[4][4];
#pragma unroll
    for (int ni = 0; ni < 4; ni++)
#pragma unroll
        for (int u = 0; u < 4; u++) acc[ni][u] = 0.f;

    for (int kt = 0; kt < LLEN / 32; kt++) {
        const int stage = kt & 1;
        if (kt + 1 < LLEN / 32) {
            int row = t >> 2, kc = (t & 3) * 8;
            cp16(&Bs[(stage ^ 1) * 64 * PAD + row * PAD + kc],
                 vTb + (size_t)row * LLEN + (kt + 1) * 32 + kc);
            CP_COMMIT();
        }
        const __half* Bc = Bs + stage * 64 * PAD;
#pragma unroll
        for (int ks = 0; ks < 2; ks++) {
            const int k0 = kt * 32 + ks * 16;
            unsigned af[4], bf[4][2];
            const __half* abase = P + (wm * 16 + g) * PSTR + k0 + tg * 2;
            af[0] = *(const unsigned*)abase;
            af[1] = *(const unsigned*)(abase + 8 * PSTR);
            af[2] = *(const unsigned*)(abase + 8);
            af[3] = *(const unsigned*)(abase + 8 * PSTR + 8);
#pragma unroll
            for (int ni = 0; ni < 4; ni++) {
                const __half* bbase = Bc + (wn * 32 + ni * 8 + g) * PAD + ks * 16 + tg * 2;
                bf[ni][0] = *(const unsigned*)bbase;
                bf[ni][1] = *(const unsigned*)(bbase + 8);
            }
#pragma unroll
            for (int ni = 0; ni < 4; ni++)
                mma16816(acc[ni], af, bf[ni]);
        }
        if (kt + 1 < LLEN / 32) {
            CP_WAIT0();
            __syncthreads();
        }
    }

    // epilogue -> ctx16[b, i, h*64 + d]
    __half* Cb = g_ctx16 + (size_t)b * LLEN * HIDN + h * DHEAD;
    const int r0 = m0 + wm * 16 + g;
#pragma unroll
    for (int ni = 0; ni < 4; ni++) {
        const int cb = wn * 32 + ni * 8 + tg * 2;
        float* ac = acc[ni];
        *(__half2*)(Cb + (size_t)r0 * HIDN + cb)       = __floats2half2_rn(ac[0], ac[1]);
        *(__half2*)(Cb + (size_t)(r0 + 8) * HIDN + cb) = __floats2half2_rn(ac[2], ac[3]);
    }
}

// ---------------------------------------------------------------------------
// Transpose V per (b,h): vT[bh][d][j] = v16[b*384+j][h*64+d]
// ---------------------------------------------------------------------------
__global__ __launch_bounds__(256) void transpose_v() {
    __shared__ __half tile[64][72];
    const int z = blockIdx.y, b = z >> 3, h = z & 7;
    const int j0 = blockIdx.x * 64;
    const int t = threadIdx.x;
#pragma unroll
    for (int it = 0; it < 2; it++) {
        int idx = t + it * 256;
        int j = idx >> 3, ch = idx & 7;
        uint4 val = *(const uint4*)(g_v16 + (size_t)(b * LLEN + j0 + j) * HIDN + h * 64 + ch * 8);
        *(uint4*)&tile[j][ch * 8] = val;
    }
    __syncthreads();
#pragma unroll
    for (int it = 0; it < 2; it++) {
        int idx = t + it * 256;
        int d = idx >> 3, ch = idx & 7;
        __half tmp[8];
#pragma unroll
        for (int u = 0; u < 8; u++) tmp[u] = tile[ch * 8 + u][d];
        *(uint4*)(g_vT + (size_t)(z * 64 + d) * LLEN + j0 + ch * 8) = *(uint4*)tmp;
    }
}

// ---------------------------------------------------------------------------
// Launcher
// ---------------------------------------------------------------------------
extern "C" void kernel_launch(void* const* d_in, const int* in_sizes, int n_in,
                              void* d_out, int out_size) {
    const float* key    = (const float*)d_in[0];
    const float* query  = (const float*)d_in[1];
    const float* value  = (const float*)d_in[2];
    const int*   seqlen = (const int*)  d_in[3];
    const float* pe     = (const float*)d_in[4];
    const float* Wk = (const float*)d_in[5],  *bk = (const float*)d_in[6];
    const float* Wq = (const float*)d_in[7],  *bq = (const float*)d_in[8];
    const float* Wv = (const float*)d_in[9],  *bv = (const float*)d_in[10];
    const float* Wr = (const float*)d_in[11], *br = (const float*)d_in[12];
    const float* u_bias = (const float*)d_in[13];
    const float* v_bias = (const float*)d_in[14];
    const float* Wf = (const float*)d_in[15], *bf = (const float*)d_in[16];
    float* out = (float*)d_out;

    __half *xk, *xq, *xv, *pe16, *wq16, *wk16, *wv16, *wr16, *wf16;
    __half *qu, *qv, *k16, *v16, *r16, *ctx16;
    cudaGetSymbolAddress((void**)&xk,   g_xk);
    cudaGetSymbolAddress((void**)&xq,   g_xq);
    cudaGetSymbolAddress((void**)&xv,   g_xv);
    cudaGetSymbolAddress((void**)&pe16, g_pe16);
    cudaGetSymbolAddress((void**)&wq16, g_wq16);
    cudaGetSymbolAddress((void**)&wk16, g_wk16);
    cudaGetSymbolAddress((void**)&wv16, g_wv16);
    cudaGetSymbolAddress((void**)&wr16, g_wr16);
    cudaGetSymbolAddress((void**)&wf16, g_wf16);
    cudaGetSymbolAddress((void**)&qu,   g_qu);
    cudaGetSymbolAddress((void**)&qv,   g_qv);
    cudaGetSymbolAddress((void**)&k16,  g_k16);
    cudaGetSymbolAddress((void**)&v16,  g_v16);
    cudaGetSymbolAddress((void**)&r16,  g_r16);
    cudaGetSymbolAddress((void**)&ctx16,g_ctx16);

    // dynamic smem for fused softmax+PV
    const int dynBytes = (64 * PSTR + 2 * 64 * PAD) * (int)sizeof(__half);
    cudaFuncSetAttribute(softpv_kernel, cudaFuncAttributeMaxDynamicSharedMemorySize, dynBytes);

    // 1. convert everything to fp16
    CvtArgs ca;
    ca.src[0] = key;   ca.dst[0] = xk;   ca.n[0] = BB*LLEN*HIDN;
    ca.src[1] = query; ca.dst[1] = xq;   ca.n[1] = BB*LLEN*HIDN;
    ca.src[2] = value; ca.dst[2] = xv;   ca.n[2] = BB*LLEN*HIDN;
    ca.src[3] = pe;    ca.dst[3] = pe16; ca.n[3] = PROWS*HIDN;
    ca.src[4] = Wq;    ca.dst[4] = wq16; ca.n[4] = HIDN*HIDN;
    ca.src[5] = Wk;    ca.dst[5] = wk16; ca.n[5] = HIDN*HIDN;
    ca.src[6] = Wv;    ca.dst[6] = wv16; ca.n[6] = HIDN*HIDN;
    ca.src[7] = Wr;    ca.dst[7] = wr16; ca.n[7] = HIDN*HIDN;
    ca.src[8] = Wf;    ca.dst[8] = wf16; ca.n[8] = HIDN*HIDN;
    cvt_kernel<<<dim3(768, 9), 256>>>(ca);

    // 2. merged projections: Q (dual, pre-scaled), K, V, R
    ProjArgs pj;
    pj.A[0] = xq;   pj.B[0] = wq16; pj.C0[0] = qu;  pj.C1[0] = qv;
    pj.bias[0] = bq; pj.mtiles[0] = 24; pj.epi[0] = 0;
    pj.A[1] = xk;   pj.B[1] = wk16; pj.C0[1] = k16; pj.C1[1] = nullptr;
    pj.bias[1] = bk; pj.mtiles[1] = 24; pj.epi[1] = 1;
    pj.A[2] = xv;   pj.B[2] = wv16; pj.C0[2] = v16; pj.C1[2] = nullptr;
    pj.bias[2] = bv; pj.mtiles[2] = 24; pj.epi[2] = 1;
    pj.A[3] = pe16; pj.B[3] = wr16; pj.C0[3] = r16; pj.C1[3] = nullptr;
    pj.bias[3] = br; pj.mtiles[3] = 6;  pj.epi[3] = 1;
    pj.ub = u_bias; pj.vb = v_bias;
    proj_kernel<<<dim3(HIDN / BN, 24, 4), 256>>>(pj);

    // 3. transpose V
    transpose_v<<<dim3(LLEN / 64, NBH), 256>>>();

    // 4. scores v2 (A-stationary): A (z<64) + S (z>=64)
    score_kernel<<<dim3(LLEN / 128, 128), 256>>>();

    // 5. fused softmax + PV -> ctx16
    softpv_kernel<<<dim3(LLEN / 64, NBH), 256, dynBytes>>>(seqlen);

    // 6. final projection -> fp32 out
    ProjArgs pf;
    pf.A[0] = ctx16; pf.B[0] = wf16; pf.C0[0] = out; pf.C1[0] = nullptr;
    pf.bias[0] = bf; pf.mtiles[0] = 24; pf.epi[0] = 2;
    pf.ub = nullptr; pf.vb = nullptr;
    pf.A[1] = pf.A[2] = pf.A[3] = nullptr;
    pf.B[1] = pf.B[2] = pf.B[3] = nullptr;
    pf.C0[1] = pf.C0[2] = pf.C0[3] = nullptr;
    pf.C1[1] = pf.C1[2] = pf.C1[3] = nullptr;
    pf.bias[1] = pf.bias[2] = pf.bias[3] = nullptr;
    pf.mtiles[1] = pf.mtiles[2] = pf.mtiles[3] = 0;
    pf.epi[1] = pf.epi[2] = pf.epi[3] = 0;
    proj_kernel<<<dim3(HIDN / BN, 24, 1), 256>>>(pf);
}